// round 9
// baseline (speedup 1.0000x reference)
#include <cuda_runtime.h>
#include <math.h>

#define H 4096
#define S 4096
#define NROWS (3 * H)   // 12288 rows per weight matrix
#define NCHUNK 32       // act/scan chunks (H / 128)

// Scratch (allocation-free rule: __device__ globals)
__device__ float g_y_ih[NROWS];
__device__ float g_y_hh[NROWS];
__device__ float g_P[S];         // chunk-local inclusive prefix of a[]
__device__ float g_bsum[NCHUNK];
__device__ float g_boff[NCHUNK]; // exclusive prefix of chunk sums

// ---------------------------------------------------------------------------
// Kernel 1: fused dual GEMV, one warp per row, 8 rows / 256-thread block
// (best measured config: 64.5us / 6.3 TB/s). Single fma chain, unroll 8.
// __ldcs keeps 402 MB of read-once weights from thrashing L2.
// ---------------------------------------------------------------------------
__global__ void __launch_bounds__(256) gemv_kernel(
    const float* __restrict__ x, const float* __restrict__ hidden,
    const float* __restrict__ w_ih, const float* __restrict__ w_hh,
    const float* __restrict__ b_ih, const float* __restrict__ b_hh)
{
    __shared__ float4 vs[H / 4];   // 16 KB

    const int rowBase = blockIdx.x * 8;
    const bool isIH = rowBase < NROWS;   // blocks never straddle: 12288 % 8 == 0

    const float* vec = isIH ? x : hidden;
    for (int i = threadIdx.x; i < H / 4; i += blockDim.x)
        vs[i] = reinterpret_cast<const float4*>(vec)[i];
    __syncthreads();

    const int warp = threadIdx.x >> 5;
    const int lane = threadIdx.x & 31;
    const int r    = rowBase + warp;
    const int lr   = isIH ? r : (r - NROWS);

    const float* W    = isIH ? w_ih : w_hh;
    const float* bias = isIH ? b_ih : b_hh;
    float*       yout = isIH ? g_y_ih : g_y_hh;

    const float4* wrow = reinterpret_cast<const float4*>(W + (size_t)lr * H);

    float acc = 0.0f;
#pragma unroll 8
    for (int i = lane; i < H / 4; i += 32) {
        float4 w4 = __ldcs(&wrow[i]);
        float4 v4 = vs[i];
        acc = fmaf(w4.x, v4.x, acc);
        acc = fmaf(w4.y, v4.y, acc);
        acc = fmaf(w4.z, v4.z, acc);
        acc = fmaf(w4.w, v4.w, acc);
    }
#pragma unroll
    for (int off = 16; off > 0; off >>= 1)
        acc += __shfl_down_sync(0xffffffffu, acc, off);

    if (lane == 0)
        yout[lr] = acc + bias[lr];
}

// ---------------------------------------------------------------------------
// Kernel 2a: GRU elementwise + chunk-local inclusive scan (32 x 128).
// ---------------------------------------------------------------------------
__global__ void __launch_bounds__(128) act_kernel(const float* __restrict__ hidden)
{
    __shared__ float warp_sums[4];

    const int tid  = threadIdx.x;
    const int lane = tid & 31;
    const int wid  = tid >> 5;
    const int j    = blockIdx.x * 128 + tid;

    const float i_r = g_y_ih[j];
    const float i_z = g_y_ih[j + H];
    const float i_n = g_y_ih[j + 2 * H];
    const float h_r = g_y_hh[j];
    const float h_z = g_y_hh[j + H];
    const float h_n = g_y_hh[j + 2 * H];

    const float rg = 1.0f / (1.0f + __expf(-(i_r + h_r)));
    const float zg = 1.0f / (1.0f + __expf(-(i_z + h_z)));
    const float ng = tanhf(i_n + rg * h_n);
    const float b  = (1.0f - zg) * hidden[j] + zg * ng;
    float a = fmaxf(b, 0.0f);

    float t = a;
#pragma unroll
    for (int off = 1; off < 32; off <<= 1) {
        float n = __shfl_up_sync(0xffffffffu, t, off);
        if (lane >= off) t += n;
    }
    if (lane == 31) warp_sums[wid] = t;
    __syncthreads();

    float base = 0.0f;
#pragma unroll
    for (int w = 0; w < 4; w++)
        if (w < wid) base += warp_sums[w];

    g_P[j] = base + t;
    if (tid == 127)
        g_bsum[blockIdx.x] = base + t;
}

// ---------------------------------------------------------------------------
// Kernel 2b: one warp scans 32 chunk sums into exclusive offsets.
// ---------------------------------------------------------------------------
__global__ void scan_sums_kernel()
{
    const int lane = threadIdx.x;
    const float v = g_bsum[lane];
    float t = v;
#pragma unroll
    for (int off = 1; off < 32; off <<= 1) {
        float n = __shfl_up_sync(0xffffffffu, t, off);
        if (lane >= off) t += n;
    }
    g_boff[lane] = t - v;   // exclusive
}

// ---------------------------------------------------------------------------
// Kernel 3: outputs[t][j] = P[t] + hidden[(j - t - 1) mod H].
// Grid (S/8, 4): 8 t-rows per block, j-dimension split 4 ways -> 2048 blocks
// for parallelism (this kernel is latency-bound, occ was the limiter).
// Each thread: one j-group; load a 16-float ALIGNED hidden window
// (4x LDG.128, mod H per quad) and assemble all eight output float4s from
// registers. Phase d = s & 3 is block-uniform -> static-index branches.
// ---------------------------------------------------------------------------
template <int D>
__device__ __forceinline__ void emit_rows8(
    const float f[16], const float p[8], float* __restrict__ out,
    int j4, int t0, int write_tail, float* __restrict__ tail)
{
#pragma unroll
    for (int r = 0; r < 8; r++) {
        float4 v;
        v.x = p[r] + f[D + 7 - r + 0];
        v.y = p[r] + f[D + 7 - r + 1];
        v.z = p[r] + f[D + 7 - r + 2];
        v.w = p[r] + f[D + 7 - r + 3];
        reinterpret_cast<float4*>(out + (size_t)(t0 + r) * H)[j4] = v;
        if (write_tail && (t0 + r) == S - 1)
            reinterpret_cast<float4*>(tail)[j4] = v;
    }
}

__global__ void __launch_bounds__(256) write_kernel(
    const float* __restrict__ hidden, float* __restrict__ out, int write_tail)
{
    const int t0   = blockIdx.x * 8;
    const int off0 = H - 1 - t0;            // in [7, 4095]
    const int d    = (off0 - 7) & 3;        // block-uniform phase (j is 4-aligned)

    float p[8];
#pragma unroll
    for (int r = 0; r < 8; r++)
        p[r] = g_P[t0 + r] + g_boff[(t0 + r) >> 7];

    float* tail = out + (size_t)S * H;

    const int j4 = blockIdx.y * 256 + threadIdx.x;   // [0, 1024)
    const int j  = j4 * 4;
    const int s  = j + off0 - 7;                     // >= 0
    const int a0 = s & ~3;

    float f[16];
    float4 f0 = __ldg(reinterpret_cast<const float4*>(hidden + ((a0)      & (H - 1))));
    float4 f1 = __ldg(reinterpret_cast<const float4*>(hidden + ((a0 + 4)  & (H - 1))));
    float4 f2 = __ldg(reinterpret_cast<const float4*>(hidden + ((a0 + 8)  & (H - 1))));
    float4 f3 = __ldg(reinterpret_cast<const float4*>(hidden + ((a0 + 12) & (H - 1))));
    f[0]  = f0.x; f[1]  = f0.y; f[2]  = f0.z; f[3]  = f0.w;
    f[4]  = f1.x; f[5]  = f1.y; f[6]  = f1.z; f[7]  = f1.w;
    f[8]  = f2.x; f[9]  = f2.y; f[10] = f2.z; f[11] = f2.w;
    f[12] = f3.x; f[13] = f3.y; f[14] = f3.z; f[15] = f3.w;

    switch (d) {
        case 0: emit_rows8<0>(f, p, out, j4, t0, write_tail, tail); break;
        case 1: emit_rows8<1>(f, p, out, j4, t0, write_tail, tail); break;
        case 2: emit_rows8<2>(f, p, out, j4, t0, write_tail, tail); break;
        default: emit_rows8<3>(f, p, out, j4, t0, write_tail, tail); break;
    }
}

extern "C" void kernel_launch(void* const* d_in, const int* in_sizes, int n_in,
                              void* d_out, int out_size)
{
    const float* x      = (const float*)d_in[0];
    const float* hidden = (const float*)d_in[1];
    const float* w_ih   = (const float*)d_in[2];
    const float* w_hh   = (const float*)d_in[3];
    const float* b_ih   = (const float*)d_in[4];
    const float* b_hh   = (const float*)d_in[5];
    float* out = (float*)d_out;

    const int write_tail = ((long long)out_size - (long long)S * H) >= H ? 1 : 0;

    gemv_kernel<<<(2 * NROWS) / 8, 256>>>(x, hidden, w_ih, w_hh, b_ih, b_hh);
    act_kernel<<<NCHUNK, 128>>>(hidden);
    scan_sums_kernel<<<1, 32>>>();
    write_kernel<<<dim3(S / 8, 4), 256>>>(hidden, out, write_tail);
}

// round 14
// speedup vs baseline: 1.0208x; 1.0208x over previous
#include <cuda_runtime.h>
#include <math.h>

#define H 4096
#define S 4096
#define NROWS (3 * H)   // 12288 rows per weight matrix
#define NCHUNK 32       // act/scan chunks (H / 128)

// Scratch (allocation-free rule: __device__ globals)
__device__ float g_y_ih[NROWS];
__device__ float g_y_hh[NROWS];
__device__ float g_P[S];         // chunk-local inclusive prefix of a[]
__device__ float g_bsum[NCHUNK]; // per-chunk totals

// ---------------------------------------------------------------------------
// Kernel 1: fused dual GEMV, one warp per row, 8 rows / 256-thread block
// (best measured config: 64.5us / 6.3 TB/s). Single fma chain, unroll 8.
// __ldcs keeps 402 MB of read-once weights from thrashing L2.
// ---------------------------------------------------------------------------
__global__ void __launch_bounds__(256) gemv_kernel(
    const float* __restrict__ x, const float* __restrict__ hidden,
    const float* __restrict__ w_ih, const float* __restrict__ w_hh,
    const float* __restrict__ b_ih, const float* __restrict__ b_hh)
{
    __shared__ float4 vs[H / 4];   // 16 KB

    const int rowBase = blockIdx.x * 8;
    const bool isIH = rowBase < NROWS;   // blocks never straddle: 12288 % 8 == 0

    const float* vec = isIH ? x : hidden;
    for (int i = threadIdx.x; i < H / 4; i += blockDim.x)
        vs[i] = reinterpret_cast<const float4*>(vec)[i];
    __syncthreads();

    const int warp = threadIdx.x >> 5;
    const int lane = threadIdx.x & 31;
    const int r    = rowBase + warp;
    const int lr   = isIH ? r : (r - NROWS);

    const float* W    = isIH ? w_ih : w_hh;
    const float* bias = isIH ? b_ih : b_hh;
    float*       yout = isIH ? g_y_ih : g_y_hh;

    const float4* wrow = reinterpret_cast<const float4*>(W + (size_t)lr * H);

    float acc = 0.0f;
#pragma unroll 8
    for (int i = lane; i < H / 4; i += 32) {
        float4 w4 = __ldcs(&wrow[i]);
        float4 v4 = vs[i];
        acc = fmaf(w4.x, v4.x, acc);
        acc = fmaf(w4.y, v4.y, acc);
        acc = fmaf(w4.z, v4.z, acc);
        acc = fmaf(w4.w, v4.w, acc);
    }
#pragma unroll
    for (int off = 16; off > 0; off >>= 1)
        acc += __shfl_down_sync(0xffffffffu, acc, off);

    if (lane == 0)
        yout[lr] = acc + bias[lr];
}

// ---------------------------------------------------------------------------
// Kernel 2: GRU elementwise + chunk-local inclusive scan (32 x 128).
// g_P gets the within-chunk inclusive prefix; g_bsum each chunk's total.
// ---------------------------------------------------------------------------
__global__ void __launch_bounds__(128) act_kernel(const float* __restrict__ hidden)
{
    __shared__ float warp_sums[4];

    const int tid  = threadIdx.x;
    const int lane = tid & 31;
    const int wid  = tid >> 5;
    const int j    = blockIdx.x * 128 + tid;

    const float i_r = g_y_ih[j];
    const float i_z = g_y_ih[j + H];
    const float i_n = g_y_ih[j + 2 * H];
    const float h_r = g_y_hh[j];
    const float h_z = g_y_hh[j + H];
    const float h_n = g_y_hh[j + 2 * H];

    const float rg = 1.0f / (1.0f + __expf(-(i_r + h_r)));
    const float zg = 1.0f / (1.0f + __expf(-(i_z + h_z)));
    const float ng = tanhf(i_n + rg * h_n);
    const float b  = (1.0f - zg) * hidden[j] + zg * ng;
    float a = fmaxf(b, 0.0f);

    float t = a;
#pragma unroll
    for (int off = 1; off < 32; off <<= 1) {
        float n = __shfl_up_sync(0xffffffffu, t, off);
        if (lane >= off) t += n;
    }
    if (lane == 31) warp_sums[wid] = t;
    __syncthreads();

    float base = 0.0f;
#pragma unroll
    for (int w = 0; w < 4; w++)
        if (w < wid) base += warp_sums[w];

    g_P[j] = base + t;
    if (tid == 127)
        g_bsum[blockIdx.x] = base + t;
}

// ---------------------------------------------------------------------------
// Kernel 3: outputs[t][j] = P[t] + hidden[(j - t - 1) mod H].
// Grid (S/8, 4), 256 threads: 8 t-rows per block, j split 4 ways.
// Cross-chunk offset is computed IN-KERNEL per warp: one 128B load of
// g_bsum + masked butterfly reduce (t0..t0+7 never straddles a 128-chunk).
// p[0..7] comes from two float4 loads (g_P is contiguous & 32B-aligned).
// hidden window: 16 aligned floats via 4x LDG.128; 8 output float4s are
// assembled in registers; phase d = s & 3 is block-uniform.
// ---------------------------------------------------------------------------
template <int D>
__device__ __forceinline__ void emit_rows8(
    const float f[16], const float p[8], float* __restrict__ out,
    int j4, int t0, int write_tail, float* __restrict__ tail)
{
#pragma unroll
    for (int r = 0; r < 8; r++) {
        float4 v;
        v.x = p[r] + f[D + 7 - r + 0];
        v.y = p[r] + f[D + 7 - r + 1];
        v.z = p[r] + f[D + 7 - r + 2];
        v.w = p[r] + f[D + 7 - r + 3];
        reinterpret_cast<float4*>(out + (size_t)(t0 + r) * H)[j4] = v;
        if (write_tail && (t0 + r) == S - 1)
            reinterpret_cast<float4*>(tail)[j4] = v;
    }
}

__global__ void __launch_bounds__(256) write_kernel(
    const float* __restrict__ hidden, float* __restrict__ out, int write_tail)
{
    const int t0    = blockIdx.x * 8;
    const int chunk = t0 >> 7;              // all 8 rows share one chunk
    const int off0  = H - 1 - t0;           // in [7, 4095]
    const int d     = (off0 - 7) & 3;       // block-uniform phase (j is 4-aligned)
    const int lane  = threadIdx.x & 31;

    // boff = exclusive prefix of chunk sums up to `chunk` (warp-redundant)
    float bv = (lane < chunk) ? g_bsum[lane] : 0.0f;
#pragma unroll
    for (int off = 16; off > 0; off >>= 1)
        bv += __shfl_xor_sync(0xffffffffu, bv, off);

    const float4 pa = *reinterpret_cast<const float4*>(g_P + t0);
    const float4 pb = *reinterpret_cast<const float4*>(g_P + t0 + 4);
    float p[8];
    p[0] = pa.x + bv; p[1] = pa.y + bv; p[2] = pa.z + bv; p[3] = pa.w + bv;
    p[4] = pb.x + bv; p[5] = pb.y + bv; p[6] = pb.z + bv; p[7] = pb.w + bv;

    float* tail = out + (size_t)S * H;

    const int j4 = blockIdx.y * 256 + threadIdx.x;   // [0, 1024)
    const int j  = j4 * 4;
    const int s  = j + off0 - 7;                     // >= 0
    const int a0 = s & ~3;

    float f[16];
    float4 f0 = __ldg(reinterpret_cast<const float4*>(hidden + ((a0)      & (H - 1))));
    float4 f1 = __ldg(reinterpret_cast<const float4*>(hidden + ((a0 + 4)  & (H - 1))));
    float4 f2 = __ldg(reinterpret_cast<const float4*>(hidden + ((a0 + 8)  & (H - 1))));
    float4 f3 = __ldg(reinterpret_cast<const float4*>(hidden + ((a0 + 12) & (H - 1))));
    f[0]  = f0.x; f[1]  = f0.y; f[2]  = f0.z; f[3]  = f0.w;
    f[4]  = f1.x; f[5]  = f1.y; f[6]  = f1.z; f[7]  = f1.w;
    f[8]  = f2.x; f[9]  = f2.y; f[10] = f2.z; f[11] = f2.w;
    f[12] = f3.x; f[13] = f3.y; f[14] = f3.z; f[15] = f3.w;

    switch (d) {
        case 0: emit_rows8<0>(f, p, out, j4, t0, write_tail, tail); break;
        case 1: emit_rows8<1>(f, p, out, j4, t0, write_tail, tail); break;
        case 2: emit_rows8<2>(f, p, out, j4, t0, write_tail, tail); break;
        default: emit_rows8<3>(f, p, out, j4, t0, write_tail, tail); break;
    }
}

extern "C" void kernel_launch(void* const* d_in, const int* in_sizes, int n_in,
                              void* d_out, int out_size)
{
    const float* x      = (const float*)d_in[0];
    const float* hidden = (const float*)d_in[1];
    const float* w_ih   = (const float*)d_in[2];
    const float* w_hh   = (const float*)d_in[3];
    const float* b_ih   = (const float*)d_in[4];
    const float* b_hh   = (const float*)d_in[5];
    float* out = (float*)d_out;

    const int write_tail = ((long long)out_size - (long long)S * H) >= H ? 1 : 0;

    gemv_kernel<<<(2 * NROWS) / 8, 256>>>(x, hidden, w_ih, w_hh, b_ih, b_hh);
    act_kernel<<<NCHUNK, 128>>>(hidden);
    write_kernel<<<dim3(S / 8, 4), 256>>>(hidden, out, write_tail);
}